// round 5
// baseline (speedup 1.0000x reference)
#include <cuda_runtime.h>

// Problem constants (fixed by reference)
#define CN 64
#define HN 256
#define WN 256
#define L0N 1024   // g0 length (y samples), output innermost dim (j)
#define L1N 1024   // g1 length (x samples), output middle dim (i)
#define AC (-0.75f)

#define JT 64      // j-tile width per block
#define RS 66      // smem row stride in floats: 66 mod 32 = 2 -> 2-way STS conflict, float2-aligned
#define NB 256     // x0 bins

// Precomputed y tap indices / weights
__device__ int4   g_yidx[L0N];
__device__ float4 g_ywt [L0N];
// x samples sorted by x0 bin (counting sort)
__device__ int    g_binstart[NB + 1];
__device__ float4 g_swx[L1N];   // weights in sorted order
__device__ int    g_si [L1N];   // original i in sorted order

__device__ __forceinline__ void cubic_w(float t, float* w) {
    // Matches reference _cubic_weights exactly (A = -0.75)
    float t2 = t * t;
    float t3 = t2 * t;
    w[0] = AC * (t3 - 2.0f * t2 + t);
    w[1] = (AC + 2.0f) * t3 - (AC + 3.0f) * t2 + 1.0f;
    float s  = 1.0f - t;
    float s2 = s * s;
    w[2] = (AC + 2.0f) * s2 * s - (AC + 3.0f) * s2 + 1.0f;
    float u = 1.0f + s;
    w[3] = AC * (u * u * u) - 5.0f * AC * (u * u) + 8.0f * AC * u - 4.0f * AC;
}

// Single-block prep: y tables + counting sort of x samples by x0 (parallel scan).
__global__ void prep_kernel(const float* __restrict__ g0,
                            const float* __restrict__ g1) {
    __shared__ int sh_hist[NB];
    __shared__ int sh_scan[NB];
    __shared__ int sh_base[NB];
    const int tid = threadIdx.x;   // 0..1023

    // --- y taps ---
    {
        float x  = (g0[tid] + 1.0f) * 0.5f * (float)(HN - 1);
        float x0 = floorf(x);
        float t  = x - x0;
        int  i0  = (int)x0;
        float w[4];
        cubic_w(t, w);
        int idx[4];
#pragma unroll
        for (int b = 0; b < 4; b++) idx[b] = min(max(i0 - 1 + b, 0), HN - 1);
        g_yidx[tid] = make_int4(idx[0], idx[1], idx[2], idx[3]);
        g_ywt [tid] = make_float4(w[0], w[1], w[2], w[3]);
    }

    // --- x taps: bin by x0, counting sort ---
    float x  = (g1[tid] + 1.0f) * 0.5f * (float)(WN - 1);
    float x0 = floorf(x);
    float t  = x - x0;
    int bin  = min(max((int)x0, 0), NB - 1);
    float w[4];
    cubic_w(t, w);

    if (tid < NB) sh_hist[tid] = 0;
    __syncthreads();
    int rank = atomicAdd(&sh_hist[bin], 1);
    __syncthreads();

    // Parallel inclusive scan (Hillis-Steele) over 256 bins
    if (tid < NB) sh_scan[tid] = sh_hist[tid];
    __syncthreads();
#pragma unroll
    for (int off = 1; off < NB; off <<= 1) {
        int v = 0;
        if (tid < NB && tid >= off) v = sh_scan[tid - off];
        __syncthreads();
        if (tid < NB) sh_scan[tid] += v;
        __syncthreads();
    }
    if (tid < NB) {
        int base = sh_scan[tid] - sh_hist[tid];   // exclusive
        sh_base[tid] = base;
        g_binstart[tid] = base;
        if (tid == NB - 1) g_binstart[NB] = sh_scan[tid];
    }
    __syncthreads();

    int pos = sh_base[bin] + rank;
    g_swx[pos] = make_float4(w[0], w[1], w[2], w[3]);
    g_si [pos] = tid;
}

// Fused kernel: one block = (c, 64-wide j tile).
// Phase A: sY[x][jl] = sum_b wy[j][b] * v[c][yi[j][b]][x]
// Phase B: each warp sweeps 16 CONSECUTIVE x0-bins keeping the 4 tap rows in
//          registers; each new bin loads only ONE new row (rotation).
__global__ void __launch_bounds__(512, 3)
fused_kernel(const float* __restrict__ v, float* __restrict__ out) {
    extern __shared__ float sY[];          // [256][RS]

    const int tid  = threadIdx.x;
    const int lane = tid & 31;
    const int wid  = tid >> 5;             // 0..15
    const int jt = blockIdx.x * JT;        // j tile base
    const int c  = blockIdx.y;

    const float* vc = v + (size_t)c * (HN * WN);

    // ---- Phase A: y-interpolation into smem ----
#pragma unroll
    for (int r = 0; r < 4; r++) {
        const int jl = wid + r * 16;       // 0..63
        const int4   yi = g_yidx[jt + jl];
        const float4 wy = g_ywt [jt + jl];
        const float* r0 = vc + yi.x * WN;
        const float* r1 = vc + yi.y * WN;
        const float* r2 = vc + yi.z * WN;
        const float* r3 = vc + yi.w * WN;
#pragma unroll
        for (int xc = 0; xc < 8; xc++) {
            const int x = xc * 32 + lane;
            float acc = wy.x * __ldg(r0 + x)
                      + wy.y * __ldg(r1 + x)
                      + wy.z * __ldg(r2 + x)
                      + wy.w * __ldg(r3 + x);
            sY[x * RS + jl] = acc;
        }
    }
    __syncthreads();

    // ---- Phase B: sequential bins with register rotation ----
    const int jq = lane * 2;               // j offset in tile: 0..62
    float* outc = out + ((size_t)c * L1N) * L0N + jt + jq;
    const float* sYj = sY + jq;

    const int b0 = wid * 16;               // this warp's first bin

    float2 a0 = *(const float2*)(sYj + max(b0 - 1, 0) * RS);
    float2 a1 = *(const float2*)(sYj + b0 * RS);
    float2 a2 = *(const float2*)(sYj + (b0 + 1) * RS);

    int s = g_binstart[b0];

#pragma unroll
    for (int bb = 0; bb < 16; bb++) {
        const int b = b0 + bb;
        const float2 a3 = *(const float2*)(sYj + min(b + 2, WN - 1) * RS);
        const int e = g_binstart[b + 1];

        int k = s;
        for (; k + 1 < e; k += 2) {
            const int    iA  = g_si [k];
            const float4 wxA = g_swx[k];
            const int    iB  = g_si [k + 1];
            const float4 wxB = g_swx[k + 1];
            float2 accA, accB;
            accA.x = wxA.x * a0.x + wxA.y * a1.x + wxA.z * a2.x + wxA.w * a3.x;
            accA.y = wxA.x * a0.y + wxA.y * a1.y + wxA.z * a2.y + wxA.w * a3.y;
            accB.x = wxB.x * a0.x + wxB.y * a1.x + wxB.z * a2.x + wxB.w * a3.x;
            accB.y = wxB.x * a0.y + wxB.y * a1.y + wxB.z * a2.y + wxB.w * a3.y;
            *(float2*)(outc + (size_t)iA * L0N) = accA;
            *(float2*)(outc + (size_t)iB * L0N) = accB;
        }
        if (k < e) {
            const int    i  = g_si [k];
            const float4 wx = g_swx[k];
            float2 acc;
            acc.x = wx.x * a0.x + wx.y * a1.x + wx.z * a2.x + wx.w * a3.x;
            acc.y = wx.x * a0.y + wx.y * a1.y + wx.z * a2.y + wx.w * a3.y;
            *(float2*)(outc + (size_t)i * L0N) = acc;
        }
        s = e;
        a0 = a1; a1 = a2; a2 = a3;
    }
}

extern "C" void kernel_launch(void* const* d_in, const int* in_sizes, int n_in,
                              void* d_out, int out_size) {
    const float* values = (const float*)d_in[0];   // (1,64,256,256)
    const float* g0     = (const float*)d_in[1];   // (1024,)
    const float* g1     = (const float*)d_in[2];   // (1024,)
    float* out = (float*)d_out;                    // (1,64,1024,1024)

    static int smem_set = 0;
    const int smem_bytes = HN * RS * sizeof(float);  // 256*66*4 = 67584
    if (!smem_set) {
        cudaFuncSetAttribute(fused_kernel,
                             cudaFuncAttributeMaxDynamicSharedMemorySize,
                             smem_bytes);
        smem_set = 1;
    }

    prep_kernel<<<1, 1024>>>(g0, g1);

    dim3 grid(L0N / JT, CN);               // (16, 64) = 1024 blocks
    fused_kernel<<<grid, 512, smem_bytes>>>(values, out);
}

// round 6
// speedup vs baseline: 1.0062x; 1.0062x over previous
#include <cuda_runtime.h>

// Problem constants (fixed by reference)
#define CN 64
#define HN 256
#define WN 256
#define L0N 1024   // g0 length (y samples), output innermost dim (j)
#define L1N 1024   // g1 length (x samples), output middle dim (i)
#define AC (-0.75f)

#define JT 128     // j-tile width per block (one float4 per lane covers it)
#define NB 256     // x0 bins

// smem: sY[x][f] where f = j/4 (float4 units), XOR-swizzled: f_stored = f ^ (x & 31).
// Row = 512 B (32 float4), conflict-free for scalar STS (lanes along x) and LDS.128.
#define SROW 128   // floats per row

// Precomputed y tap indices / weights
__device__ int4   g_yidx[L0N];
__device__ float4 g_ywt [L0N];
// x samples sorted by x0 bin (counting sort)
__device__ int    g_binstart[NB + 1];
__device__ float4 g_swx[L1N];   // weights in sorted order
__device__ int    g_si [L1N];   // original i in sorted order

__device__ __forceinline__ void cubic_w(float t, float* w) {
    // Matches reference _cubic_weights exactly (A = -0.75)
    float t2 = t * t;
    float t3 = t2 * t;
    w[0] = AC * (t3 - 2.0f * t2 + t);
    w[1] = (AC + 2.0f) * t3 - (AC + 3.0f) * t2 + 1.0f;
    float s  = 1.0f - t;
    float s2 = s * s;
    w[2] = (AC + 2.0f) * s2 * s - (AC + 3.0f) * s2 + 1.0f;
    float u = 1.0f + s;
    w[3] = AC * (u * u * u) - 5.0f * AC * (u * u) + 8.0f * AC * u - 4.0f * AC;
}

// Single-block prep: y tables + counting sort of x samples by x0 (parallel scan).
__global__ void prep_kernel(const float* __restrict__ g0,
                            const float* __restrict__ g1) {
    __shared__ int sh_hist[NB];
    __shared__ int sh_scan[NB];
    __shared__ int sh_base[NB];
    const int tid = threadIdx.x;   // 0..1023

    // --- y taps ---
    {
        float x  = (g0[tid] + 1.0f) * 0.5f * (float)(HN - 1);
        float x0 = floorf(x);
        float t  = x - x0;
        int  i0  = (int)x0;
        float w[4];
        cubic_w(t, w);
        int idx[4];
#pragma unroll
        for (int b = 0; b < 4; b++) idx[b] = min(max(i0 - 1 + b, 0), HN - 1);
        g_yidx[tid] = make_int4(idx[0], idx[1], idx[2], idx[3]);
        g_ywt [tid] = make_float4(w[0], w[1], w[2], w[3]);
    }

    // --- x taps: bin by x0, counting sort ---
    float x  = (g1[tid] + 1.0f) * 0.5f * (float)(WN - 1);
    float x0 = floorf(x);
    float t  = x - x0;
    int bin  = min(max((int)x0, 0), NB - 1);
    float w[4];
    cubic_w(t, w);

    if (tid < NB) sh_hist[tid] = 0;
    __syncthreads();
    int rank = atomicAdd(&sh_hist[bin], 1);
    __syncthreads();

    // Parallel inclusive scan (Hillis-Steele) over 256 bins
    if (tid < NB) sh_scan[tid] = sh_hist[tid];
    __syncthreads();
#pragma unroll
    for (int off = 1; off < NB; off <<= 1) {
        int v = 0;
        if (tid < NB && tid >= off) v = sh_scan[tid - off];
        __syncthreads();
        if (tid < NB) sh_scan[tid] += v;
        __syncthreads();
    }
    if (tid < NB) {
        int base = sh_scan[tid] - sh_hist[tid];   // exclusive
        sh_base[tid] = base;
        g_binstart[tid] = base;
        if (tid == NB - 1) g_binstart[NB] = sh_scan[tid];
    }
    __syncthreads();

    int pos = sh_base[bin] + rank;
    g_swx[pos] = make_float4(w[0], w[1], w[2], w[3]);
    g_si [pos] = tid;
}

// Fused kernel: one block = (c, 128-wide j tile), 1024 threads, 128 KB smem.
// Phase A: sY[x][j] = sum_b wy[j][b] * v[c][yi[j][b]][x]   (swizzled store)
// Phase B: warp sweeps 8 consecutive x0-bins, 4 tap rows held as float4 regs
//          (rotation: 1 LDS.128 per bin). One STG.128 per output row per warp.
__global__ void __launch_bounds__(1024, 1)
fused_kernel(const float* __restrict__ v, float* __restrict__ out) {
    extern __shared__ float sY[];          // [256][128] swizzled

    const int tid  = threadIdx.x;
    const int lane = tid & 31;
    const int wid  = tid >> 5;             // 0..31
    const int jt = blockIdx.x * JT;        // j tile base
    const int c  = blockIdx.y;

    const float* vc = v + (size_t)c * (HN * WN);

    // ---- Phase A: y-interpolation into swizzled smem ----
    // Warp handles j = jt + wid*4 + jj; lanes along x (coalesced v reads,
    // conflict-free swizzled STS).
#pragma unroll
    for (int jj = 0; jj < 4; jj++) {
        const int jl = (wid << 2) + jj;    // 0..127
        const int4   yi = g_yidx[jt + jl];
        const float4 wy = g_ywt [jt + jl];
        const float* r0 = vc + yi.x * WN;
        const float* r1 = vc + yi.y * WN;
        const float* r2 = vc + yi.z * WN;
        const float* r3 = vc + yi.w * WN;
        const int f    = jl >> 2;          // float4 index 0..31
        const int jsub = jl & 3;
#pragma unroll
        for (int xc = 0; xc < 8; xc++) {
            const int x = xc * 32 + lane;
            float acc = wy.x * __ldg(r0 + x)
                      + wy.y * __ldg(r1 + x)
                      + wy.z * __ldg(r2 + x)
                      + wy.w * __ldg(r3 + x);
            // swizzled scalar store: float index = x*128 + (f ^ (x&31))*4 + jsub
            sY[x * SROW + ((f ^ (x & 31)) << 2) + jsub] = acc;
        }
    }
    __syncthreads();

    // ---- Phase B: 8 consecutive bins per warp, float4 register rotation ----
    // Lane owns logical float4 f = lane (j = jt + lane*4 .. +3).
    float* outc = out + ((size_t)c * L1N) * L0N + jt + (lane << 2);

    const int b0 = wid * 8;                // this warp's first bin

    // swizzled row load: row x, logical f = lane
    #define LOADROW(x) (*(const float4*)(sY + (x) * SROW + ((lane ^ ((x) & 31)) << 2)))

    float4 a0 = LOADROW(max(b0 - 1, 0));
    float4 a1 = LOADROW(b0);
    float4 a2 = LOADROW(b0 + 1);           // b0 <= 248, no clamp needed

    int s = g_binstart[b0];

#pragma unroll
    for (int bb = 0; bb < 8; bb++) {
        const int b = b0 + bb;
        const float4 a3 = LOADROW(min(b + 2, WN - 1));
        const int e = g_binstart[b + 1];

        int k = s;
        for (; k + 1 < e; k += 2) {
            const int    iA  = g_si [k];
            const float4 wxA = g_swx[k];
            const int    iB  = g_si [k + 1];
            const float4 wxB = g_swx[k + 1];
            float4 accA, accB;
            accA.x = wxA.x * a0.x + wxA.y * a1.x + wxA.z * a2.x + wxA.w * a3.x;
            accA.y = wxA.x * a0.y + wxA.y * a1.y + wxA.z * a2.y + wxA.w * a3.y;
            accA.z = wxA.x * a0.z + wxA.y * a1.z + wxA.z * a2.z + wxA.w * a3.z;
            accA.w = wxA.x * a0.w + wxA.y * a1.w + wxA.z * a2.w + wxA.w * a3.w;
            accB.x = wxB.x * a0.x + wxB.y * a1.x + wxB.z * a2.x + wxB.w * a3.x;
            accB.y = wxB.x * a0.y + wxB.y * a1.y + wxB.z * a2.y + wxB.w * a3.y;
            accB.z = wxB.x * a0.z + wxB.y * a1.z + wxB.z * a2.z + wxB.w * a3.z;
            accB.w = wxB.x * a0.w + wxB.y * a1.w + wxB.z * a2.w + wxB.w * a3.w;
            *(float4*)(outc + (size_t)iA * L0N) = accA;
            *(float4*)(outc + (size_t)iB * L0N) = accB;
        }
        if (k < e) {
            const int    i  = g_si [k];
            const float4 wx = g_swx[k];
            float4 acc;
            acc.x = wx.x * a0.x + wx.y * a1.x + wx.z * a2.x + wx.w * a3.x;
            acc.y = wx.x * a0.y + wx.y * a1.y + wx.z * a2.y + wx.w * a3.y;
            acc.z = wx.x * a0.z + wx.y * a1.z + wx.z * a2.z + wx.w * a3.z;
            acc.w = wx.x * a0.w + wx.y * a1.w + wx.z * a2.w + wx.w * a3.w;
            *(float4*)(outc + (size_t)i * L0N) = acc;
        }
        s = e;
        a0 = a1; a1 = a2; a2 = a3;
    }
    #undef LOADROW
}

extern "C" void kernel_launch(void* const* d_in, const int* in_sizes, int n_in,
                              void* d_out, int out_size) {
    const float* values = (const float*)d_in[0];   // (1,64,256,256)
    const float* g0     = (const float*)d_in[1];   // (1024,)
    const float* g1     = (const float*)d_in[2];   // (1024,)
    float* out = (float*)d_out;                    // (1,64,1024,1024)

    static int smem_set = 0;
    const int smem_bytes = HN * SROW * sizeof(float);  // 256*128*4 = 131072
    if (!smem_set) {
        cudaFuncSetAttribute(fused_kernel,
                             cudaFuncAttributeMaxDynamicSharedMemorySize,
                             smem_bytes);
        smem_set = 1;
    }

    prep_kernel<<<1, 1024>>>(g0, g1);

    dim3 grid(L0N / JT, CN);               // (8, 64) = 512 blocks
    fused_kernel<<<grid, 1024, smem_bytes>>>(values, out);
}